// round 3
// baseline (speedup 1.0000x reference)
#include <cuda_runtime.h>
#include <cuda_bf16.h>
#include <cstdint>

#define N_TOKENS 16384
#define HIDDEN   4096
#define NE       192   // 3 * 64 experts
#define E        64

// ---------------- scratch (static device arrays are allowed) ----------------
__device__ __nv_bfloat16 g_w_hi[NE * HIDDEN];
__device__ __nv_bfloat16 g_w_lo[NE * HIDDEN];
__device__ float         g_mixT[(size_t)NE * N_TOKENS];  // transposed mix [col][token]

// ---------------- helpers ----------------------------------------------------
__device__ __forceinline__ uint32_t smem_u32(const void* p) {
    uint32_t a;
    asm("{ .reg .u64 t; cvta.to.shared.u64 t, %1; cvt.u32.u64 %0, t; }" : "=r"(a) : "l"(p));
    return a;
}

__device__ __forceinline__ void sts64(uint32_t addr, uint32_t a, uint32_t b) {
    asm volatile("st.shared.v2.b32 [%0], {%1, %2};" :: "r"(addr), "r"(a), "r"(b));
}
__device__ __forceinline__ void sts128(uint32_t addr, uint4 v) {
    asm volatile("st.shared.v4.b32 [%0], {%1, %2, %3, %4};"
                 :: "r"(addr), "r"(v.x), "r"(v.y), "r"(v.z), "r"(v.w));
}

__device__ __forceinline__ void ldmatrix_x4(uint32_t* r, uint32_t addr) {
    asm volatile("ldmatrix.sync.aligned.m8n8.x4.shared.b16 {%0,%1,%2,%3}, [%4];"
                 : "=r"(r[0]), "=r"(r[1]), "=r"(r[2]), "=r"(r[3]) : "r"(addr));
}
__device__ __forceinline__ void ldmatrix_x2(uint32_t* r, uint32_t addr) {
    asm volatile("ldmatrix.sync.aligned.m8n8.x2.shared.b16 {%0,%1}, [%2];"
                 : "=r"(r[0]), "=r"(r[1]) : "r"(addr));
}

__device__ __forceinline__ void mma_bf16(float* d, const uint32_t* a, const uint32_t* b) {
    asm volatile(
        "mma.sync.aligned.m16n8k16.row.col.f32.bf16.bf16.f32 "
        "{%0,%1,%2,%3}, {%4,%5,%6,%7}, {%8,%9}, {%0,%1,%2,%3};"
        : "+f"(d[0]), "+f"(d[1]), "+f"(d[2]), "+f"(d[3])
        : "r"(a[0]), "r"(a[1]), "r"(a[2]), "r"(a[3]), "r"(b[0]), "r"(b[1]));
}

__device__ __forceinline__ float ex2_approx(float x) {
    float y;
    asm("ex2.approx.f32 %0, %1;" : "=f"(y) : "f"(x));
    return y;
}

__device__ __forceinline__ uint32_t pack_bf16_hi2(float x0, float x1,
                                                  uint32_t& lo_out) {
    __nv_bfloat16 h0 = __float2bfloat16(x0);
    __nv_bfloat16 h1 = __float2bfloat16(x1);
    __nv_bfloat16 l0 = __float2bfloat16(x0 - __bfloat162float(h0));
    __nv_bfloat16 l1 = __float2bfloat16(x1 - __bfloat162float(h1));
    lo_out = ((uint32_t)__bfloat16_as_ushort(l1) << 16) | __bfloat16_as_ushort(l0);
    return ((uint32_t)__bfloat16_as_ushort(h1) << 16) | __bfloat16_as_ushort(h0);
}

// ---------------- kernel 1: split W into bf16 hi/lo --------------------------
__global__ void prep_w_kernel(const float* __restrict__ W) {
    int i = blockIdx.x * blockDim.x + threadIdx.x;
    if (i < NE * HIDDEN) {
        float x = W[i];
        __nv_bfloat16 h = __float2bfloat16(x);
        g_w_hi[i] = h;
        g_w_lo[i] = __float2bfloat16(x - __bfloat162float(h));
    }
}

// ---------------- kernel 2: GEMM mixT = (A @ W^T)^T via mma.sync bf16 -------
// CTA tile: 128 tokens x 192 cols, BK=32. 8 warps: warp tile 32 x 96.
// SMEM per stage (rows padded to 80B for conflict-free ldmatrix):
//   a_hi 128*80, a_lo 128*80, b_hi 192*80, b_lo 192*80 = 51200 B; x2 stages.
static constexpr int BK        = 32;
static constexpr int NSTEP     = HIDDEN / BK;          // 128
static constexpr int A_HI_OFF  = 0;
static constexpr int A_LO_OFF  = 128 * 80;             // 10240
static constexpr int B_HI_OFF  = 2 * 128 * 80;         // 20480
static constexpr int B_LO_OFF  = B_HI_OFF + 192 * 80;  // 35840
static constexpr int STAGE_SZ  = B_LO_OFF + 192 * 80;  // 51200
static constexpr int GEMM_SMEM = 2 * STAGE_SZ;         // 102400

__global__ void __launch_bounds__(256, 1)
gemm_kernel(const float* __restrict__ A) {
    extern __shared__ char smem[];
    const uint32_t sb  = smem_u32(smem);
    const int tid      = threadIdx.x;
    const int wid      = tid >> 5;
    const int lid      = tid & 31;
    const int mbase    = blockIdx.x * 128;
    const int m0       = (wid >> 1) * 32;   // warp M offset within CTA tile
    const int n0       = (wid & 1) * 96;    // warp N offset

    float acc[2][12][4];
    #pragma unroll
    for (int mt = 0; mt < 2; ++mt)
        #pragma unroll
        for (int n = 0; n < 12; ++n)
            #pragma unroll
            for (int j = 0; j < 4; ++j) acc[mt][n][j] = 0.f;

    // staging registers
    float4 va[4];
    uint4  vbh[3], vbl[3];

    // G2R index precompute
    const int a_row = tid >> 3, a_q = tid & 7;           // + i*32 rows per i
    const int b_row = tid >> 2, b_u = tid & 3;           // + i*64 rows per i

    auto g2r = [&](int kt) {
        const float4* Ag = reinterpret_cast<const float4*>(
            A + (size_t)(mbase) * HIDDEN + kt * BK);
        #pragma unroll
        for (int i = 0; i < 4; ++i)
            va[i] = Ag[(size_t)(a_row + i * 32) * (HIDDEN / 4) + a_q];
        const char* whp = reinterpret_cast<const char*>(g_w_hi);
        const char* wlp = reinterpret_cast<const char*>(g_w_lo);
        #pragma unroll
        for (int i = 0; i < 3; ++i) {
            size_t byt = ((size_t)(b_row + i * 64) * HIDDEN + kt * BK + b_u * 8) * 2;
            vbh[i] = *reinterpret_cast<const uint4*>(whp + byt);
            vbl[i] = *reinterpret_cast<const uint4*>(wlp + byt);
        }
    };

    auto r2s = [&](int stage) {
        const uint32_t st = sb + stage * STAGE_SZ;
        #pragma unroll
        for (int i = 0; i < 4; ++i) {
            uint32_t l01, l23;
            uint32_t h01 = pack_bf16_hi2(va[i].x, va[i].y, l01);
            uint32_t h23 = pack_bf16_hi2(va[i].z, va[i].w, l23);
            uint32_t off = (uint32_t)((a_row + i * 32) * 80 + a_q * 8);
            sts64(st + A_HI_OFF + off, h01, h23);
            sts64(st + A_LO_OFF + off, l01, l23);
        }
        #pragma unroll
        for (int i = 0; i < 3; ++i) {
            uint32_t off = (uint32_t)((b_row + i * 64) * 80 + b_u * 16);
            sts128(st + B_HI_OFF + off, vbh[i]);
            sts128(st + B_LO_OFF + off, vbl[i]);
        }
    };

    // ldmatrix lane addresses (relative offsets fixed per thread)
    const uint32_t a_lane_row = (uint32_t)(m0 + (lid & 15));
    const uint32_t a_lane_col = (uint32_t)(((lid >> 4) & 1) * 16);
    const uint32_t b_lane_row = (uint32_t)(n0 + (lid & 7));
    const uint32_t b_lane_col = (uint32_t)(((lid >> 3) & 1) * 16);

    auto compute = [&](int stage) {
        const uint32_t st = sb + stage * STAGE_SZ;
        #pragma unroll
        for (int h = 0; h < 2; ++h) {   // two k16 halves of BK=32
            uint32_t ah[2][4], al[2][4];
            #pragma unroll
            for (int mt = 0; mt < 2; ++mt) {
                uint32_t aoff = (a_lane_row + mt * 16) * 80 + a_lane_col + h * 32;
                ldmatrix_x4(ah[mt], st + A_HI_OFF + aoff);
                ldmatrix_x4(al[mt], st + A_LO_OFF + aoff);
            }
            #pragma unroll
            for (int n = 0; n < 12; ++n) {
                uint32_t bh[2], bl[2];
                uint32_t boff = (b_lane_row + n * 8) * 80 + b_lane_col + h * 32;
                ldmatrix_x2(bh, st + B_HI_OFF + boff);
                ldmatrix_x2(bl, st + B_LO_OFF + boff);
                #pragma unroll
                for (int mt = 0; mt < 2; ++mt) {
                    mma_bf16(acc[mt][n], ah[mt], bh);   // hi*hi
                    mma_bf16(acc[mt][n], ah[mt], bl);   // hi*lo
                    mma_bf16(acc[mt][n], al[mt], bh);   // lo*hi
                }
            }
        }
    };

    // software pipeline: ping-pong smem stages
    g2r(0);
    r2s(0);
    __syncthreads();
    for (int kt = 0; kt < NSTEP; ++kt) {
        if (kt + 1 < NSTEP) g2r(kt + 1);
        compute(kt & 1);
        if (kt + 1 < NSTEP) r2s((kt + 1) & 1);
        __syncthreads();
    }

    // write transposed result: g_mixT[col][token]
    const int d_row = lid >> 2;          // 0..7
    const int d_col = (lid & 3) * 2;     // 0,2,4,6
    #pragma unroll
    for (int mt = 0; mt < 2; ++mt) {
        #pragma unroll
        for (int n = 0; n < 12; ++n) {
            int tok = mbase + m0 + mt * 16 + d_row;
            int col = n0 + n * 8 + d_col;
            g_mixT[(size_t)col * N_TOKENS + tok]           = acc[mt][n][0];
            g_mixT[(size_t)(col + 1) * N_TOKENS + tok]     = acc[mt][n][1];
            g_mixT[(size_t)col * N_TOKENS + tok + 8]       = acc[mt][n][2];
            g_mixT[(size_t)(col + 1) * N_TOKENS + tok + 8] = acc[mt][n][3];
        }
    }
}

// ---------------- kernel 3: per-token softmax attention ----------------------
// smem: kv[64][66] float2 (33792 B) then q2[64][64] float (16384 B)
static constexpr int EPI_SMEM = 64 * 66 * 8 + 64 * 64 * 4;

__global__ void __launch_bounds__(256)
epi_kernel(float* __restrict__ out) {
    extern __shared__ char smem[];
    float2* kv = reinterpret_cast<float2*>(smem);
    float*  q2 = reinterpret_cast<float*>(smem + 64 * 66 * 8);
    const int tid = threadIdx.x;
    const int T0 = blockIdx.x * 64;
    const float LOG2E = 1.4426950408889634f;

    #pragma unroll
    for (int i = 0; i < 12; ++i) {
        int idx = i * 256 + tid;      // 0..3071
        int col = idx >> 4;           // 0..191
        int t = (idx & 15) * 4;       // 0..60
        float4 v = *reinterpret_cast<const float4*>(&g_mixT[(size_t)col * N_TOKENS + T0 + t]);
        if (col < 64) {
            q2[(t + 0) * 64 + col] = v.x * LOG2E;
            q2[(t + 1) * 64 + col] = v.y * LOG2E;
            q2[(t + 2) * 64 + col] = v.z * LOG2E;
            q2[(t + 3) * 64 + col] = v.w * LOG2E;
        } else if (col < 128) {
            int f = col - 64;
            kv[(t + 0) * 66 + f].x = v.x;
            kv[(t + 1) * 66 + f].x = v.y;
            kv[(t + 2) * 66 + f].x = v.z;
            kv[(t + 3) * 66 + f].x = v.w;
        } else {
            int f = col - 128;
            kv[(t + 0) * 66 + f].y = v.x;
            kv[(t + 1) * 66 + f].y = v.y;
            kv[(t + 2) * 66 + f].y = v.z;
            kv[(t + 3) * 66 + f].y = v.w;
        }
    }
    __syncthreads();

    const int token = tid >> 2;   // 4 threads per token
    const int g = tid & 3;        // each owns 16 experts
    const float2* kvt = kv + token * 66;
    const float*  q2t = q2 + token * 64;
    float* outt = out + (size_t)(T0 + token) * E;

    for (int ei = 0; ei < 16; ei += 2) {
        int e0 = g * 16 + ei;
        float qa = q2t[e0], qb = q2t[e0 + 1];
        float Za = 0.f, Zb = 0.f, Sa = 0.f, Sb = 0.f;
        #pragma unroll 16
        for (int f = 0; f < E; ++f) {
            float2 p = kvt[f];
            float ta = ex2_approx(qa * p.x);
            float tb = ex2_approx(qb * p.x);
            Za += ta; Sa = fmaf(ta, p.y, Sa);
            Zb += tb; Sb = fmaf(tb, p.y, Sb);
        }
        outt[e0]     = __fdividef(Sa, Za);
        outt[e0 + 1] = __fdividef(Sb, Zb);
    }
}

// ---------------- launch -----------------------------------------------------
extern "C" void kernel_launch(void* const* d_in, const int* in_sizes, int n_in,
                              void* d_out, int out_size) {
    const float* hidden = (const float*)d_in[0];   // [16384, 4096] f32
    const float* W      = (const float*)d_in[1];   // [192, 4096]  f32
    float* out          = (float*)d_out;           // [16384, 64]  f32

    cudaFuncSetAttribute(gemm_kernel, cudaFuncAttributeMaxDynamicSharedMemorySize, GEMM_SMEM);
    cudaFuncSetAttribute(epi_kernel,  cudaFuncAttributeMaxDynamicSharedMemorySize, EPI_SMEM);

    prep_w_kernel<<<(NE * HIDDEN + 255) / 256, 256>>>(W);
    gemm_kernel<<<N_TOKENS / 128, 256, GEMM_SMEM>>>(hidden);
    epi_kernel<<<N_TOKENS / 64, 256, EPI_SMEM>>>(out);
}